// round 15
// baseline (speedup 1.0000x reference)
#include <cuda_runtime.h>
#include <cuda_bf16.h>
#include <cstdint>

#define T_  512
#define NS_ 32
#define H_  128

// Pre-fragmented weights: [ (n*2+jh) ][ frag f = mt*20 + part*10 + kc ][ lane ] -> uint4
__device__ uint4 g_W[(size_t)64 * 320 * 32];

// ---- smem layout (bytes) ----
#define SW_OFF   0          // 320 frags * 32 lanes * 16 B = 163840
#define V_OFF    163840     // 2 bufs * (hi 7680 + lo 7680) = 30720 ; row = 24 u32, 80 rows
#define SD_OFF   194560     // 256 rows * 17 f32 = 17408
#define SRED_OFF 211968     // [buf][jh][16] f32 = 256
#define SMEM_BYTES 212224

static __device__ __forceinline__ uint32_t s2u(const void* p) {
    uint32_t a;
    asm("{ .reg .u64 t; cvta.to.shared.u64 t, %1; cvt.u32.u64 %0, t; }" : "=r"(a) : "l"(p));
    return a;
}
static __device__ __forceinline__ uint32_t mapa_(uint32_t a, uint32_t r) {
    uint32_t o;
    asm("mapa.shared::cluster.u32 %0, %1, %2;" : "=r"(o) : "r"(a), "r"(r));
    return o;
}
static __device__ __forceinline__ void stc32(uint32_t a, uint32_t v) {
    asm volatile("st.shared::cluster.b32 [%0], %1;" :: "r"(a), "r"(v) : "memory");
}
static __device__ __forceinline__ float sigm_(float x) {
    float e = __expf(-x), r;
    asm("rcp.approx.f32 %0, %1;" : "=f"(r) : "f"(1.0f + e));
    return r;
}
static __device__ __forceinline__ float tanh_(float x) {
    return fmaf(2.0f, sigm_(2.0f * x), -1.0f);
}
#define MMA(D, A, B0, B1) asm volatile( \
    "mma.sync.aligned.m16n8k16.row.col.f32.bf16.bf16.f32 " \
    "{%0,%1,%2,%3}, {%4,%5,%6,%7}, {%8,%9}, {%0,%1,%2,%3};" \
    : "+f"((D)[0]), "+f"((D)[1]), "+f"((D)[2]), "+f"((D)[3]) \
    : "r"((A).x), "r"((A).y), "r"((A).z), "r"((A).w), "r"(B0), "r"(B1))
#define CSYNC() do { asm volatile("barrier.cluster.arrive.aligned;" ::: "memory"); \
                     asm volatile("barrier.cluster.wait.aligned;" ::: "memory"); } while (0)

// ---------------- prep: weights -> per-lane mma fragments, bf16 hi/lo ----------------
__global__ void prep_k(const float* __restrict__ Whh, const float* __restrict__ Wih) {
    const int nb = blockIdx.y;                 // n*2 + jh
    const int n = nb >> 1, jh = nb & 1;
    const int f = blockIdx.x;                  // mt*20 + part*10 + kc
    const int mt = f / 20, rem = f % 20, part = rem / 10, kc = rem % 10;
    const int l = threadIdx.x, gid = l >> 2, tid4 = l & 3;

    auto bits = [&](int r, int k) -> uint32_t {
        int g = r >> 6, jj = r & 63;
        int grow = g * 128 + jh * 64 + jj;
        float w = (k < 128) ? Whh[((size_t)n * 512 + grow) * 128 + k]
                            : Wih[((size_t)n * 512 + grow) * 32 + (k - 128)];
        __nv_bfloat16 hi = __float2bfloat16(w);
        __nv_bfloat16 v  = part ? __float2bfloat16(w - __bfloat162float(hi)) : hi;
        return (uint32_t)__bfloat16_as_ushort(v);
    };
    const int r0 = mt * 16 + gid, r1 = r0 + 8;
    const int k0 = kc * 16 + tid4 * 2, k2 = k0 + 8;
    uint4 frag;
    frag.x = bits(r0, k0) | (bits(r0, k0 + 1) << 16);
    frag.y = bits(r1, k0) | (bits(r1, k0 + 1) << 16);
    frag.z = bits(r0, k2) | (bits(r0, k2 + 1) << 16);
    frag.w = bits(r1, k2) | (bits(r1, k2 + 1) << 16);
    g_W[((size_t)nb * 320 + f) * 32 + l] = frag;
}

// ---------------- main persistent cluster kernel ----------------
__global__ void __launch_bounds__(512, 1) __cluster_dims__(2, 1, 1)
lstm_mma(const float* __restrict__ X, const float* __restrict__ bih,
         const float* __restrict__ bhh, const float* __restrict__ Wout,
         const float* __restrict__ bout, float* __restrict__ out) {
    extern __shared__ __align__(16) char smem[];
    const uint32_t sb = s2u(smem);
    const int tid = threadIdx.x, w = tid >> 5, l = tid & 31;
    const int gid = l >> 2, tid4 = l & 3;
    uint32_t jh;
    asm("mov.u32 %0, %%cluster_ctarank;" : "=r"(jh));
    const int pairIdx = blockIdx.x >> 1;
    const int n = pairIdx & 31, bh = pairIdx >> 5;

    // ---- load pre-fragmented weights (160 KB) ----
    {
        const uint4* src = g_W + (size_t)(n * 2 + (int)jh) * 320 * 32;
        uint4* dst = (uint4*)smem;
        for (int i = tid; i < 320 * 32; i += 512) dst[i] = src[i];
    }
    // ---- zero V buffers ----
    {
        uint32_t* v = (uint32_t*)(smem + V_OFF);
        for (int i = tid; i < 30720 / 4; i += 512) v[i] = 0;
    }
    // ---- biases for D1 init (warp w = M-tile w: rows 16w+gid, 16w+8+gid) ----
    float biasLo, biasHi;
    {
        int r = w * 16 + gid;
        int grow = (r >> 6) * 128 + (int)jh * 64 + (r & 63);
        biasLo = bih[n * 512 + grow] + bhh[n * 512 + grow];
        int r2 = r + 8;
        grow = (r2 >> 6) * 128 + (int)jh * 64 + (r2 & 63);
        biasHi = bih[n * 512 + grow] + bhh[n * 512 + grow];
    }
    // ---- epilogue role: warp = batch (b = w), lane = j-pair (p = l) ----
    const float wj0 = Wout[n * 128 + (int)jh * 64 + 2 * l];
    const float wj1 = Wout[n * 128 + (int)jh * 64 + 2 * l + 1];
    const float bo = bout[n];
    float cst[2] = {0.f, 0.f}, hst[2] = {0.f, 0.f};
    // ---- x role: threads 256..511 ----
    const int xi = tid - 256;
    const int xp = (xi & 15) * 2;
    const int xb = bh * 16 + (xi >> 4);
    const uint32_t xoff = (uint32_t)((64 + (xi & 15)) * 24 + (xi >> 4)) * 4;
    // ---- cluster addresses ----
    const uint32_t peerBase = mapa_(sb, jh ^ 1u);
    const uint32_t r0Base = mapa_(sb, 0u);

    __syncthreads();
    // ---- x(0) into buffer 0 ----
    if (tid >= 256) {
        float2 xv = *(const float2*)(X + ((size_t)xb * T_) * NS_ + xp);
        __nv_bfloat16 h0 = __float2bfloat16(xv.x), h1 = __float2bfloat16(xv.y);
        uint32_t xh = __bfloat16_as_ushort(h0) | ((uint32_t)__bfloat16_as_ushort(h1) << 16);
        uint32_t xl = __bfloat16_as_ushort(__float2bfloat16(xv.x - __bfloat162float(h0)))
                    | ((uint32_t)__bfloat16_as_ushort(__float2bfloat16(xv.y - __bfloat162float(h1))) << 16);
        *(uint32_t*)(smem + V_OFF + xoff) = xh;
        *(uint32_t*)(smem + V_OFF + xoff + 7680) = xl;
    }
    __syncthreads();
    CSYNC();

    float* sD = (float*)(smem + SD_OFF);
    const float* sRed = (const float*)(smem + SRED_OFF);
    const uint4* sWf = (const uint4*)smem;
    const uint32_t fb = (uint32_t)(w * 20) * 32 + l;

    for (int t = 0; t < T_; t++) {
        // ---- pred(t-1) from staged head partials (rank 0) ----
        if (jh == 0 && tid < 16 && t > 0) {
            int bf = (t - 1) & 1;
            float s = sRed[bf * 32 + tid] + sRed[bf * 32 + 16 + tid] + bo;
            out[((size_t)(bh * 16 + tid) * T_ + (t - 1)) * NS_ + n] = s;
        }
        // ---- x(t+1) prefetch ----
        float2 xv = make_float2(0.f, 0.f);
        if (tid >= 256 && t + 1 < T_)
            xv = *(const float2*)(X + ((size_t)xb * T_ + t + 1) * NS_ + xp);

        // ---- MMA phase: warp w computes M-rows 16w..16w+15, 3 terms ----
        float D1[2][4], D2[2][4];
        #pragma unroll
        for (int ntl = 0; ntl < 2; ntl++) {
            D1[ntl][0] = biasLo; D1[ntl][1] = biasLo;
            D1[ntl][2] = biasHi; D1[ntl][3] = biasHi;
            D2[ntl][0] = 0.f; D2[ntl][1] = 0.f; D2[ntl][2] = 0.f; D2[ntl][3] = 0.f;
        }
        const uint32_t* svh = (const uint32_t*)(smem + V_OFF + (t & 1) * 15360);
        const uint32_t* svl = svh + 1920;
        #pragma unroll
        for (int kc = 0; kc < 10; kc++) {
            uint4 Ah = sWf[fb + kc * 32];
            uint4 Al = sWf[fb + 320 + kc * 32];
            const int rB0 = (kc * 8 + tid4) * 24, rB1 = (kc * 8 + 4 + tid4) * 24;
            #pragma unroll
            for (int ntl = 0; ntl < 2; ntl++) {
                const int col = ntl * 8 + gid;
                uint32_t bh0 = svh[rB0 + col], bh1 = svh[rB1 + col];
                uint32_t bl0 = svl[rB0 + col], bl1 = svl[rB1 + col];
                MMA(D1[ntl], Ah, bh0, bh1);
                MMA(D2[ntl], Ah, bl0, bl1);
                MMA(D2[ntl], Al, bh0, bh1);
            }
        }
        // ---- stage D to smem (stride 17, scalar 32-bit stores: alignment-safe) ----
        #pragma unroll
        for (int ntl = 0; ntl < 2; ntl++) {
            int row = w * 16 + gid, colb = ntl * 8 + tid4 * 2;
            sD[row * 17 + colb]           = D1[ntl][0] + D2[ntl][0];
            sD[row * 17 + colb + 1]       = D1[ntl][1] + D2[ntl][1];
            sD[(row + 8) * 17 + colb]     = D1[ntl][2] + D2[ntl][2];
            sD[(row + 8) * 17 + colb + 1] = D1[ntl][3] + D2[ntl][3];
        }
        __syncthreads();
        // ---- epilogue: thread (b = w, j-pair = l) ----
        {
            float pp = 0.f;
            uint32_t hhi = 0u, hlo = 0u;
            #pragma unroll
            for (int jq = 0; jq < 2; jq++) {
                const int jj = 2 * l + jq;
                float iv = sD[(jj) * 17 + w];
                float fv = sD[(64 + jj) * 17 + w];
                float gv = sD[(128 + jj) * 17 + w];
                float ov = sD[(192 + jj) * 17 + w];
                float cv = sigm_(fv) * cst[jq] + sigm_(iv) * tanh_(gv);
                cst[jq] = cv;
                float hv = sigm_(ov) * tanh_(cv);
                hst[jq] = hv;
                pp = fmaf(hv, jq ? wj1 : wj0, pp);
                __nv_bfloat16 hb = __float2bfloat16(hv);
                hhi |= ((uint32_t)__bfloat16_as_ushort(hb)) << (16 * jq);
                hlo |= ((uint32_t)__bfloat16_as_ushort(
                           __float2bfloat16(hv - __bfloat162float(hb)))) << (16 * jq);
            }
            // h(t+1) into next buffer, own + peer (V row = jh*32 + l, col = w)
            const uint32_t vbo = V_OFF + (uint32_t)(((t + 1) & 1) * 15360)
                               + (uint32_t)(((int)jh * 32 + l) * 24 + w) * 4;
            *(uint32_t*)(smem + vbo) = hhi;
            *(uint32_t*)(smem + vbo + 7680) = hlo;
            stc32(peerBase + vbo, hhi);
            stc32(peerBase + vbo + 7680, hlo);
            // x(t+1) into next buffer (local only)
            if (tid >= 256 && t + 1 < T_) {
                const uint32_t xo = V_OFF + (uint32_t)(((t + 1) & 1) * 15360) + xoff;
                __nv_bfloat16 h0 = __float2bfloat16(xv.x), h1 = __float2bfloat16(xv.y);
                uint32_t xh = __bfloat16_as_ushort(h0)
                            | ((uint32_t)__bfloat16_as_ushort(h1) << 16);
                uint32_t xl = __bfloat16_as_ushort(__float2bfloat16(xv.x - __bfloat162float(h0)))
                            | ((uint32_t)__bfloat16_as_ushort(__float2bfloat16(xv.y - __bfloat162float(h1))) << 16);
                *(uint32_t*)(smem + xo) = xh;
                *(uint32_t*)(smem + xo + 7680) = xl;
            }
            // head: reduce over all 32 j-pairs in warp, lane 0 -> rank 0
            #pragma unroll
            for (int m = 1; m <= 16; m <<= 1)
                pp += __shfl_xor_sync(0xffffffffu, pp, m);
            if (l == 0) {
                const uint32_t ro = SRED_OFF
                    + (uint32_t)(((t & 1) * 32 + (int)jh * 16 + w) * 4);
                stc32(r0Base + ro, __float_as_uint(pp));
            }
        }
        CSYNC();
    }
    // ---- pred(T-1) ----
    if (jh == 0 && tid < 16) {
        int bf = (T_ - 1) & 1;
        float s = sRed[bf * 32 + tid] + sRed[bf * 32 + 16 + tid] + bo;
        out[((size_t)(bh * 16 + tid) * T_ + (T_ - 1)) * NS_ + n] = s;
    }
    // ---- hT, cT : [N,B,H] ----
    {
        const size_t OB = (size_t)32 * T_ * NS_;
        const size_t OC = OB + (size_t)32 * 32 * 128;
        const int bgl = bh * 16 + w;
        #pragma unroll
        for (int jq = 0; jq < 2; jq++) {
            int jgl = (int)jh * 64 + 2 * l + jq;
            out[OB + ((size_t)n * 32 + bgl) * 128 + jgl] = hst[jq];
            out[OC + ((size_t)n * 32 + bgl) * 128 + jgl] = cst[jq];
        }
    }
}

extern "C" void kernel_launch(void* const* d_in, const int* in_sizes, int n_in,
                              void* d_out, int out_size) {
    const float* X    = (const float*)d_in[0];
    const float* Wih  = (const float*)d_in[1];
    const float* Whh  = (const float*)d_in[2];
    const float* bih  = (const float*)d_in[3];
    const float* bhh  = (const float*)d_in[4];
    const float* Wout = (const float*)d_in[5];
    const float* bout = (const float*)d_in[6];

    prep_k<<<dim3(320, 64), 32>>>(Whh, Wih);

    cudaFuncSetAttribute(lstm_mma, cudaFuncAttributeMaxDynamicSharedMemorySize, SMEM_BYTES);
    lstm_mma<<<128, 512, SMEM_BYTES>>>(X, bih, bhh, Wout, bout, (float*)d_out);
}

// round 16
// speedup vs baseline: 1.1564x; 1.1564x over previous
#include <cuda_runtime.h>
#include <cuda_bf16.h>
#include <cstdint>

#define T_  512
#define NS_ 32
#define H_  128

// Pre-fragmented weights: [ (n*2+jh) ][ frag f = mt*20 + part*10 + kc ][ lane ] -> uint4
__device__ uint4 g_W[(size_t)64 * 320 * 32];

// ---- smem layout (bytes) ----
#define SW_OFF   0          // 320 frags * 32 lanes * 16 B = 163840
#define V_OFF    163840     // 2 bufs * 12800 ; row = 20 u64 {hi,lo}, 80 rows (64 h + 16 x)
#define VROW     20
#define VBUF     12800
#define SD_OFF   189440     // 256 rows * 18 f32 = 18432
#define SRED_OFF 207872     // [buf parity][32] f32 = 256
#define MBAR_OFF 208128     // 2 mbarriers
#define SMEM_BYTES 208192

static __device__ __forceinline__ uint32_t s2u(const void* p) {
    uint32_t a;
    asm("{ .reg .u64 t; cvta.to.shared.u64 t, %1; cvt.u32.u64 %0, t; }" : "=r"(a) : "l"(p));
    return a;
}
static __device__ __forceinline__ uint32_t mapa_(uint32_t a, uint32_t r) {
    uint32_t o;
    asm("mapa.shared::cluster.u32 %0, %1, %2;" : "=r"(o) : "r"(a), "r"(r));
    return o;
}
static __device__ __forceinline__ void stc64(uint32_t a, unsigned long long v) {
    asm volatile("st.shared::cluster.b64 [%0], %1;" :: "r"(a), "l"(v) : "memory");
}
static __device__ __forceinline__ void mbar_arrive_cl(uint32_t a) {
    asm volatile("mbarrier.arrive.release.cluster.shared::cluster.b64 _, [%0];"
                 :: "r"(a) : "memory");
}
#define MBAR_WAIT(m, ph) asm volatile( \
    "{\n\t.reg .pred P;\n\tWL_%=:\n\t" \
    "mbarrier.try_wait.parity.acquire.cluster.shared::cta.b64 P, [%0], %1, 0x989680;\n\t" \
    "@P bra.uni WD_%=;\n\tbra.uni WL_%=;\n\tWD_%=:\n\t}" :: "r"(m), "r"(ph) : "memory")
static __device__ __forceinline__ float sigm_(float x) {
    float e = __expf(-x), r;
    asm("rcp.approx.f32 %0, %1;" : "=f"(r) : "f"(1.0f + e));
    return r;
}
static __device__ __forceinline__ float tanh_(float x) {
    return fmaf(2.0f, sigm_(2.0f * x), -1.0f);
}
#define MMA(D, A, B0, B1) asm volatile( \
    "mma.sync.aligned.m16n8k16.row.col.f32.bf16.bf16.f32 " \
    "{%0,%1,%2,%3}, {%4,%5,%6,%7}, {%8,%9}, {%0,%1,%2,%3};" \
    : "+f"((D)[0]), "+f"((D)[1]), "+f"((D)[2]), "+f"((D)[3]) \
    : "r"((A).x), "r"((A).y), "r"((A).z), "r"((A).w), "r"(B0), "r"(B1))
#define CSYNC() do { asm volatile("barrier.cluster.arrive.aligned;" ::: "memory"); \
                     asm volatile("barrier.cluster.wait.aligned;" ::: "memory"); } while (0)

// ---------------- prep: weights -> per-lane mma fragments, bf16 hi/lo ----------------
__global__ void prep_k(const float* __restrict__ Whh, const float* __restrict__ Wih) {
    const int nb = blockIdx.y;                 // n*2 + jh
    const int n = nb >> 1, jh = nb & 1;
    const int f = blockIdx.x;                  // mt*20 + part*10 + kc
    const int mt = f / 20, rem = f % 20, part = rem / 10, kc = rem % 10;
    const int l = threadIdx.x, gid = l >> 2, tid4 = l & 3;

    auto bits = [&](int r, int k) -> uint32_t {
        int g = r >> 6, jj = r & 63;
        int grow = g * 128 + jh * 64 + jj;
        float w = (k < 128) ? Whh[((size_t)n * 512 + grow) * 128 + k]
                            : Wih[((size_t)n * 512 + grow) * 32 + (k - 128)];
        __nv_bfloat16 hi = __float2bfloat16(w);
        __nv_bfloat16 v  = part ? __float2bfloat16(w - __bfloat162float(hi)) : hi;
        return (uint32_t)__bfloat16_as_ushort(v);
    };
    const int r0 = mt * 16 + gid, r1 = r0 + 8;
    const int k0 = kc * 16 + tid4 * 2, k2 = k0 + 8;
    uint4 frag;
    frag.x = bits(r0, k0) | (bits(r0, k0 + 1) << 16);
    frag.y = bits(r1, k0) | (bits(r1, k0 + 1) << 16);
    frag.z = bits(r0, k2) | (bits(r0, k2 + 1) << 16);
    frag.w = bits(r1, k2) | (bits(r1, k2 + 1) << 16);
    g_W[((size_t)nb * 320 + f) * 32 + l] = frag;
}

// ---------------- main persistent cluster kernel ----------------
__global__ void __launch_bounds__(256, 1) __cluster_dims__(2, 1, 1)
lstm_mma(const float* __restrict__ X, const float* __restrict__ bih,
         const float* __restrict__ bhh, const float* __restrict__ Wout,
         const float* __restrict__ bout, float* __restrict__ out) {
    extern __shared__ __align__(16) char smem[];
    const uint32_t sb = s2u(smem);
    const int tid = threadIdx.x, w = tid >> 5, l = tid & 31;
    const int gid = l >> 2, tid4 = l & 3;
    uint32_t jh;
    asm("mov.u32 %0, %%cluster_ctarank;" : "=r"(jh));
    const int pairIdx = blockIdx.x >> 1;
    const int n = pairIdx & 31, bh = pairIdx >> 5;

    // ---- load pre-fragmented weights (160 KB) ----
    {
        const uint4* src = g_W + (size_t)(n * 2 + (int)jh) * 320 * 32;
        uint4* dst = (uint4*)smem;
        for (int i = tid; i < 320 * 32; i += 256) dst[i] = src[i];
    }
    // ---- zero V buffers ----
    {
        uint32_t* v = (uint32_t*)(smem + V_OFF);
        for (int i = tid; i < 2 * VBUF / 4; i += 256) v[i] = 0;
    }
    // ---- mbarriers ----
    if (tid == 0) {
        asm volatile("mbarrier.init.shared.b64 [%0], %1;" :: "r"(sb + MBAR_OFF), "r"(512u) : "memory");
        asm volatile("mbarrier.init.shared.b64 [%0], %1;" :: "r"(sb + MBAR_OFF + 8), "r"(512u) : "memory");
    }
    // ---- biases for D1 init ----
    float biasLo[2], biasHi[2];
    #pragma unroll
    for (int mtl = 0; mtl < 2; mtl++) {
        int r = (2 * w + mtl) * 16 + gid;
        int grow = (r >> 6) * 128 + (int)jh * 64 + (r & 63);
        biasLo[mtl] = bih[n * 512 + grow] + bhh[n * 512 + grow];
        int r2 = r + 8;
        grow = (r2 >> 6) * 128 + (int)jh * 64 + (r2 & 63);
        biasHi[mtl] = bih[n * 512 + grow] + bhh[n * 512 + grow];
    }
    // ---- update role: thread owns j-pairs (2l, 2l+1) x batches (2w, 2w+1) ----
    const int jj0 = 2 * l, b0p = 2 * w;
    const float wj0 = Wout[n * 128 + (int)jh * 64 + jj0];
    const float wj1 = Wout[n * 128 + (int)jh * 64 + jj0 + 1];
    const float bo = bout[n];
    float cst[2][2] = {{0.f, 0.f}, {0.f, 0.f}};
    float hst[2][2] = {{0.f, 0.f}, {0.f, 0.f}};
    // ---- x role: every thread loads one (batch, series-pair) ----
    const int xp = (tid & 15) * 2;
    const int xb = bh * 16 + (tid >> 4);
    const uint32_t xoff = (uint32_t)((64 + (tid & 15)) * VROW + (tid >> 4)) * 8;
    // ---- cluster addresses ----
    const uint32_t peerBase = mapa_(sb, jh ^ 1u);
    const uint32_t r0Base = mapa_(sb, 0u);
    const uint32_t mbarLoc0 = sb + MBAR_OFF, mbarLoc1 = sb + MBAR_OFF + 8;
    const uint32_t mbarSelfC0 = mapa_(mbarLoc0, jh), mbarSelfC1 = mapa_(mbarLoc1, jh);
    const uint32_t mbarPeerC0 = mapa_(mbarLoc0, jh ^ 1u), mbarPeerC1 = mapa_(mbarLoc1, jh ^ 1u);

    __syncthreads();
    // ---- x(0) into buffer 0 ----
    {
        float2 xv = *(const float2*)(X + ((size_t)xb * T_) * NS_ + xp);
        __nv_bfloat16 h0 = __float2bfloat16(xv.x), h1 = __float2bfloat16(xv.y);
        uint32_t xh = __bfloat16_as_ushort(h0) | ((uint32_t)__bfloat16_as_ushort(h1) << 16);
        uint32_t xl = __bfloat16_as_ushort(__float2bfloat16(xv.x - __bfloat162float(h0)))
                    | ((uint32_t)__bfloat16_as_ushort(__float2bfloat16(xv.y - __bfloat162float(h1))) << 16);
        *(uint2*)(smem + V_OFF + xoff) = make_uint2(xh, xl);
    }
    __syncthreads();
    CSYNC();   // V(0) + mbarriers visible cluster-wide

    float* sD = (float*)(smem + SD_OFF);
    const float* sRed = (const float*)(smem + SRED_OFF);
    const uint4* sWf = (const uint4*)smem;
    const uint32_t fb0 = (uint32_t)((2 * w) * 20) * 32 + l;
    const uint32_t fb1 = (uint32_t)((2 * w + 1) * 20) * 32 + l;
    uint32_t ph2[2] = {0u, 0u};

    for (int t = 0; t < T_; t++) {
        // ---- pred(t-1) from staged head partials (rank 0) ----
        if (jh == 0 && tid < 16 && t > 0) {
            int bf = (t - 1) & 1;
            float s = sRed[bf * 32 + tid] + sRed[bf * 32 + 16 + tid] + bo;
            out[((size_t)(bh * 16 + tid) * T_ + (t - 1)) * NS_ + n] = s;
        }
        // ---- x(t+1) prefetch ----
        float2 xv = make_float2(0.f, 0.f);
        if (t + 1 < T_) xv = *(const float2*)(X + ((size_t)xb * T_ + t + 1) * NS_ + xp);

        // ---- MMA phase: D[256x16] = W(hi/lo) * V(hi/lo), 3 terms ----
        float D1[2][2][4], D2[2][2][4];
        #pragma unroll
        for (int mtl = 0; mtl < 2; mtl++)
            #pragma unroll
            for (int ntl = 0; ntl < 2; ntl++) {
                D1[mtl][ntl][0] = biasLo[mtl]; D1[mtl][ntl][1] = biasLo[mtl];
                D1[mtl][ntl][2] = biasHi[mtl]; D1[mtl][ntl][3] = biasHi[mtl];
                D2[mtl][ntl][0] = 0.f; D2[mtl][ntl][1] = 0.f;
                D2[mtl][ntl][2] = 0.f; D2[mtl][ntl][3] = 0.f;
            }
        const uint2* sv = (const uint2*)(smem + V_OFF + (t & 1) * VBUF);
        #pragma unroll
        for (int kc = 0; kc < 10; kc++) {
            uint4 Ah0 = sWf[fb0 + kc * 32];
            uint4 Ah1 = sWf[fb1 + kc * 32];
            uint4 Al0 = sWf[fb0 + 320 + kc * 32];
            uint4 Al1 = sWf[fb1 + 320 + kc * 32];
            const int rB0 = (kc * 8 + tid4) * VROW, rB1 = (kc * 8 + 4 + tid4) * VROW;
            #pragma unroll
            for (int ntl = 0; ntl < 2; ntl++) {
                const int col = ntl * 8 + gid;
                uint2 v0 = sv[rB0 + col];    // {hi, lo} k-pair row 0
                uint2 v1 = sv[rB1 + col];    // {hi, lo} k-pair row +8
                MMA(D1[0][ntl], Ah0, v0.x, v1.x);
                MMA(D1[1][ntl], Ah1, v0.x, v1.x);
                MMA(D2[0][ntl], Ah0, v0.y, v1.y);
                MMA(D2[1][ntl], Ah1, v0.y, v1.y);
                MMA(D2[0][ntl], Al0, v0.x, v1.x);
                MMA(D2[1][ntl], Al1, v0.x, v1.x);
            }
        }
        // ---- stage D to smem (stride 18, float2 aligned) ----
        #pragma unroll
        for (int mtl = 0; mtl < 2; mtl++)
            #pragma unroll
            for (int ntl = 0; ntl < 2; ntl++) {
                int row = (2 * w + mtl) * 16 + gid, colb = ntl * 8 + tid4 * 2;
                *(float2*)(sD + row * 18 + colb) =
                    make_float2(D1[mtl][ntl][0] + D2[mtl][ntl][0],
                                D1[mtl][ntl][1] + D2[mtl][ntl][1]);
                *(float2*)(sD + (row + 8) * 18 + colb) =
                    make_float2(D1[mtl][ntl][2] + D2[mtl][ntl][2],
                                D1[mtl][ntl][3] + D2[mtl][ntl][3]);
            }
        __syncthreads();
        // ---- epilogue ----
        {
            float pp0 = 0.f, pp1 = 0.f;
            uint32_t hhi[2] = {0u, 0u}, hlo[2] = {0u, 0u};
            #pragma unroll
            for (int jq = 0; jq < 2; jq++) {
                const int jj = jj0 + jq;
                float2 i2 = *(const float2*)(sD + jj * 18 + b0p);
                float2 f2 = *(const float2*)(sD + (64 + jj) * 18 + b0p);
                float2 g2 = *(const float2*)(sD + (128 + jj) * 18 + b0p);
                float2 o2 = *(const float2*)(sD + (192 + jj) * 18 + b0p);
                const float wjq = jq ? wj1 : wj0;
                #pragma unroll
                for (int bq = 0; bq < 2; bq++) {
                    float iv = bq ? i2.y : i2.x;
                    float fv = bq ? f2.y : f2.x;
                    float gv = bq ? g2.y : g2.x;
                    float ov = bq ? o2.y : o2.x;
                    float cv = sigm_(fv) * cst[jq][bq] + sigm_(iv) * tanh_(gv);
                    cst[jq][bq] = cv;
                    float hv = sigm_(ov) * tanh_(cv);
                    hst[jq][bq] = hv;
                    if (bq) pp1 = fmaf(hv, wjq, pp1); else pp0 = fmaf(hv, wjq, pp0);
                    __nv_bfloat16 hb = __float2bfloat16(hv);
                    hhi[bq] |= ((uint32_t)__bfloat16_as_ushort(hb)) << (16 * jq);
                    hlo[bq] |= ((uint32_t)__bfloat16_as_ushort(
                                 __float2bfloat16(hv - __bfloat162float(hb)))) << (16 * jq);
                }
            }
            // h(t+1) into next buffer, own + peer; V row = jh*32 + l, cols b0p, b0p+1
            const uint32_t vbo = V_OFF + (uint32_t)(((t + 1) & 1) * VBUF)
                               + (uint32_t)(((int)jh * 32 + l) * VROW + b0p) * 8;
            unsigned long long e0 = (unsigned long long)hhi[0] | ((unsigned long long)hlo[0] << 32);
            unsigned long long e1 = (unsigned long long)hhi[1] | ((unsigned long long)hlo[1] << 32);
            *(ulonglong2*)(smem + vbo) = make_ulonglong2(e0, e1);
            stc64(peerBase + vbo, e0);
            stc64(peerBase + vbo + 8, e1);
            // x(t+1) into next buffer (local only)
            if (t + 1 < T_) {
                const uint32_t xo = V_OFF + (uint32_t)(((t + 1) & 1) * VBUF) + xoff;
                __nv_bfloat16 h0 = __float2bfloat16(xv.x), h1 = __float2bfloat16(xv.y);
                uint32_t xh = __bfloat16_as_ushort(h0)
                            | ((uint32_t)__bfloat16_as_ushort(h1) << 16);
                uint32_t xl = __bfloat16_as_ushort(__float2bfloat16(xv.x - __bfloat162float(h0)))
                            | ((uint32_t)__bfloat16_as_ushort(__float2bfloat16(xv.y - __bfloat162float(h1))) << 16);
                *(uint2*)(smem + xo) = make_uint2(xh, xl);
            }
            // head partials -> rank 0
            #pragma unroll
            for (int m = 1; m <= 16; m <<= 1) {
                pp0 += __shfl_xor_sync(0xffffffffu, pp0, m);
                pp1 += __shfl_xor_sync(0xffffffffu, pp1, m);
            }
            if (l == 0) {
                const uint32_t ro = SRED_OFF
                    + (uint32_t)(((t & 1) * 32 + (int)jh * 16 + 2 * w) * 4);
                unsigned long long pv;
                asm("mov.b64 %0, {%1,%2};" : "=l"(pv) : "f"(pp0), "f"(pp1));
                stc64(r0Base + ro, pv);
            }
        }
        // ---- handshake: arrive on both CTAs' mbarriers, wait on local ----
        {
            const int mb = t & 1;
            mbar_arrive_cl(mb ? mbarSelfC1 : mbarSelfC0);
            mbar_arrive_cl(mb ? mbarPeerC1 : mbarPeerC0);
            MBAR_WAIT(mb ? mbarLoc1 : mbarLoc0, ph2[mb]);
            ph2[mb] ^= 1u;
        }
    }
    // ---- pred(T-1) ----
    if (jh == 0 && tid < 16) {
        int bf = (T_ - 1) & 1;
        float s = sRed[bf * 32 + tid] + sRed[bf * 32 + 16 + tid] + bo;
        out[((size_t)(bh * 16 + tid) * T_ + (T_ - 1)) * NS_ + n] = s;
    }
    // ---- hT, cT : [N,B,H] ----
    {
        const size_t OB = (size_t)32 * T_ * NS_;
        const size_t OC = OB + (size_t)32 * 32 * 128;
        #pragma unroll
        for (int jq = 0; jq < 2; jq++)
            #pragma unroll
            for (int bq = 0; bq < 2; bq++) {
                int bgl = bh * 16 + b0p + bq;
                int jgl = (int)jh * 64 + jj0 + jq;
                out[OB + ((size_t)n * 32 + bgl) * 128 + jgl] = hst[jq][bq];
                out[OC + ((size_t)n * 32 + bgl) * 128 + jgl] = cst[jq][bq];
            }
    }
    CSYNC();
}

extern "C" void kernel_launch(void* const* d_in, const int* in_sizes, int n_in,
                              void* d_out, int out_size) {
    const float* X    = (const float*)d_in[0];
    const float* Wih  = (const float*)d_in[1];
    const float* Whh  = (const float*)d_in[2];
    const float* bih  = (const float*)d_in[3];
    const float* bhh  = (const float*)d_in[4];
    const float* Wout = (const float*)d_in[5];
    const float* bout = (const float*)d_in[6];

    prep_k<<<dim3(320, 64), 32>>>(Whh, Wih);

    cudaFuncSetAttribute(lstm_mma, cudaFuncAttributeMaxDynamicSharedMemorySize, SMEM_BYTES);
    lstm_mma<<<128, 256, SMEM_BYTES>>>(X, bih, bhh, Wout, bout, (float*)d_out);
}

// round 17
// speedup vs baseline: 1.1566x; 1.0001x over previous
#include <cuda_runtime.h>
#include <cuda_bf16.h>
#include <cstdint>

#define T_  512
#define NS_ 32
#define H_  128

// Pre-fragmented weights: [ (n*2+jh) ][ frag f = mt*20 + part*10 + kc ][ lane ] -> uint4
__device__ uint4 g_W[(size_t)64 * 320 * 32];

// ---- smem layout (bytes) ----
#define SW_OFF   0          // 320 frags * 32 lanes * 16 B = 163840
#define V_OFF    163840     // 2 bufs * (hi 7680 + lo 7680) = 30720 ; row = 24 u32, 80 rows
#define SD_OFF   194560     // 256 * 18 f32 = 18432
#define SRED_OFF 212992     // [buf][rank][16] f32 = 256
#define MBAR_OFF 213248     // 2 mbarriers
#define SMEM_BYTES 213312

static __device__ __forceinline__ uint32_t s2u(const void* p) {
    uint32_t a;
    asm("{ .reg .u64 t; cvta.to.shared.u64 t, %1; cvt.u32.u64 %0, t; }" : "=r"(a) : "l"(p));
    return a;
}
static __device__ __forceinline__ uint32_t mapa_(uint32_t a, uint32_t r) {
    uint32_t o;
    asm("mapa.shared::cluster.u32 %0, %1, %2;" : "=r"(o) : "r"(a), "r"(r));
    return o;
}
static __device__ __forceinline__ void stc64(uint32_t a, unsigned long long v) {
    asm volatile("st.shared::cluster.b64 [%0], %1;" :: "r"(a), "l"(v) : "memory");
}
static __device__ __forceinline__ void mbar_arrive_cl(uint32_t a) {
    asm volatile("mbarrier.arrive.release.cluster.shared::cluster.b64 _, [%0];"
                 :: "r"(a) : "memory");
}
#define MBAR_WAIT(m, ph) asm volatile( \
    "{\n\t.reg .pred P;\n\tWL_%=:\n\t" \
    "mbarrier.try_wait.parity.acquire.cluster.shared::cta.b64 P, [%0], %1, 0x989680;\n\t" \
    "@P bra.uni WD_%=;\n\tbra.uni WL_%=;\n\tWD_%=:\n\t}" :: "r"(m), "r"(ph) : "memory")
static __device__ __forceinline__ float sigm_(float x) {
    float e = __expf(-x), r;
    asm("rcp.approx.f32 %0, %1;" : "=f"(r) : "f"(1.0f + e));
    return r;
}
static __device__ __forceinline__ float tanh_(float x) {
    return fmaf(2.0f, sigm_(2.0f * x), -1.0f);
}
#define MMA(D, A, B0, B1) asm volatile( \
    "mma.sync.aligned.m16n8k16.row.col.f32.bf16.bf16.f32 " \
    "{%0,%1,%2,%3}, {%4,%5,%6,%7}, {%8,%9}, {%0,%1,%2,%3};" \
    : "+f"((D)[0]), "+f"((D)[1]), "+f"((D)[2]), "+f"((D)[3]) \
    : "r"((A).x), "r"((A).y), "r"((A).z), "r"((A).w), "r"(B0), "r"(B1))
#define CSYNC() do { asm volatile("barrier.cluster.arrive.aligned;" ::: "memory"); \
                     asm volatile("barrier.cluster.wait.aligned;" ::: "memory"); } while (0)

// ---------------- prep: weights -> per-lane mma fragments, bf16 hi/lo ----------------
__global__ void prep_k(const float* __restrict__ Whh, const float* __restrict__ Wih) {
    const int nb = blockIdx.y;                 // n*2 + jh
    const int n = nb >> 1, jh = nb & 1;
    const int f = blockIdx.x;                  // mt*20 + part*10 + kc
    const int mt = f / 20, rem = f % 20, part = rem / 10, kc = rem % 10;
    const int l = threadIdx.x, gid = l >> 2, tid4 = l & 3;

    auto bits = [&](int r, int k) -> uint32_t {
        int g = r >> 6, jj = r & 63;
        int grow = g * 128 + jh * 64 + jj;
        float w = (k < 128) ? Whh[((size_t)n * 512 + grow) * 128 + k]
                            : Wih[((size_t)n * 512 + grow) * 32 + (k - 128)];
        __nv_bfloat16 hi = __float2bfloat16(w);
        __nv_bfloat16 v  = part ? __float2bfloat16(w - __bfloat162float(hi)) : hi;
        return (uint32_t)__bfloat16_as_ushort(v);
    };
    const int r0 = mt * 16 + gid, r1 = r0 + 8;
    const int k0 = kc * 16 + tid4 * 2, k2 = k0 + 8;
    uint4 frag;
    frag.x = bits(r0, k0) | (bits(r0, k0 + 1) << 16);
    frag.y = bits(r1, k0) | (bits(r1, k0 + 1) << 16);
    frag.z = bits(r0, k2) | (bits(r0, k2 + 1) << 16);
    frag.w = bits(r1, k2) | (bits(r1, k2 + 1) << 16);
    g_W[((size_t)nb * 320 + f) * 32 + l] = frag;
}

// ---------------- main persistent cluster kernel ----------------
__global__ void __launch_bounds__(256, 1) __cluster_dims__(2, 1, 1)
lstm_mma(const float* __restrict__ X, const float* __restrict__ bih,
         const float* __restrict__ bhh, const float* __restrict__ Wout,
         const float* __restrict__ bout, float* __restrict__ out) {
    extern __shared__ __align__(16) char smem[];
    const uint32_t sb = s2u(smem);
    const int tid = threadIdx.x, w = tid >> 5, l = tid & 31;
    const int gid = l >> 2, tid4 = l & 3;
    uint32_t jh;
    asm("mov.u32 %0, %%cluster_ctarank;" : "=r"(jh));
    const int pairIdx = blockIdx.x >> 1;
    const int n = pairIdx & 31, bh = pairIdx >> 5;

    // ---- load pre-fragmented weights (160 KB) ----
    {
        const uint4* src = g_W + (size_t)(n * 2 + (int)jh) * 320 * 32;
        uint4* dst = (uint4*)smem;
        for (int i = tid; i < 320 * 32; i += 256) dst[i] = src[i];
    }
    // ---- zero V buffers ----
    {
        uint32_t* v = (uint32_t*)(smem + V_OFF);
        for (int i = tid; i < 30720 / 4; i += 256) v[i] = 0;
    }
    // ---- mbarriers: count 2 (one elected arrive per CTA) ----
    if (tid == 0) {
        asm volatile("mbarrier.init.shared.b64 [%0], %1;" :: "r"(sb + MBAR_OFF), "r"(2u) : "memory");
        asm volatile("mbarrier.init.shared.b64 [%0], %1;" :: "r"(sb + MBAR_OFF + 8), "r"(2u) : "memory");
    }
    // ---- biases for D1 init (per D-frag rows) ----
    float biasLo[2], biasHi[2];
    #pragma unroll
    for (int mtl = 0; mtl < 2; mtl++) {
        int r = (2 * w + mtl) * 16 + gid;
        int grow = (r >> 6) * 128 + (int)jh * 64 + (r & 63);
        biasLo[mtl] = bih[n * 512 + grow] + bhh[n * 512 + grow];
        int r2 = r + 8;
        grow = (r2 >> 6) * 128 + (int)jh * 64 + (r2 & 63);
        biasHi[mtl] = bih[n * 512 + grow] + bhh[n * 512 + grow];
    }
    // ---- update-role constants (thread owns jj0,jj0+1 x b0p,b0p+1) ----
    const int jj0 = 2 * l, b0p = 2 * w;
    const float wj0 = Wout[n * 128 + (int)jh * 64 + jj0];
    const float wj1 = Wout[n * 128 + (int)jh * 64 + jj0 + 1];
    const float bo = bout[n];
    float cst[2][2] = {{0.f, 0.f}, {0.f, 0.f}};
    float hst[2][2] = {{0.f, 0.f}, {0.f, 0.f}};
    // ---- x-role constants ----
    const int xp = (tid & 15) * 2;
    const int xb = bh * 16 + (tid >> 4);
    const uint32_t xoff = (uint32_t)((64 + (tid & 15)) * 24 + (tid >> 4)) * 4;
    // ---- cluster addresses ----
    const uint32_t peerBase = mapa_(sb, jh ^ 1u);
    const uint32_t r0Base = mapa_(sb, 0u);
    const uint32_t mbarLoc0 = sb + MBAR_OFF, mbarLoc1 = sb + MBAR_OFF + 8;
    const uint32_t mbarSelfC0 = mapa_(mbarLoc0, jh), mbarSelfC1 = mapa_(mbarLoc1, jh);
    const uint32_t mbarPeerC0 = mapa_(mbarLoc0, jh ^ 1u), mbarPeerC1 = mapa_(mbarLoc1, jh ^ 1u);

    __syncthreads();
    // ---- x(0) into buffer 0 ----
    {
        float2 xv = *(const float2*)(X + ((size_t)xb * T_) * NS_ + xp);
        __nv_bfloat16 h0 = __float2bfloat16(xv.x), h1 = __float2bfloat16(xv.y);
        uint32_t xh = __bfloat16_as_ushort(h0) | ((uint32_t)__bfloat16_as_ushort(h1) << 16);
        uint32_t xl = __bfloat16_as_ushort(__float2bfloat16(xv.x - __bfloat162float(h0)))
                    | ((uint32_t)__bfloat16_as_ushort(__float2bfloat16(xv.y - __bfloat162float(h1))) << 16);
        *(uint32_t*)(smem + V_OFF + xoff) = xh;
        *(uint32_t*)(smem + V_OFF + xoff + 7680) = xl;
    }
    __syncthreads();
    CSYNC();   // V(0) + mbarrier init visible cluster-wide

    float* sD = (float*)(smem + SD_OFF);
    float* sRed = (float*)(smem + SRED_OFF);
    const uint4* sWf = (const uint4*)smem;
    const uint32_t fb0 = (uint32_t)((2 * w) * 20) * 32 + l;
    const uint32_t fb1 = (uint32_t)((2 * w + 1) * 20) * 32 + l;
    uint32_t ph2[2] = {0u, 0u};

    for (int t = 0; t < T_; t++) {
        // ---- pred(t-1) from staged head partials (rank 0) ----
        if (jh == 0 && tid < 16 && t > 0) {
            int bf = (t - 1) & 1;
            float s = sRed[bf * 32 + tid] + sRed[bf * 32 + 16 + tid] + bo;
            out[((size_t)(bh * 16 + tid) * T_ + (t - 1)) * NS_ + n] = s;
        }
        // ---- x(t+1) prefetch ----
        float2 xv = make_float2(0.f, 0.f);
        if (t + 1 < T_) xv = *(const float2*)(X + ((size_t)xb * T_ + t + 1) * NS_ + xp);

        // ---- MMA phase: D[256x16] = W(hi/lo) * V(hi/lo), 3 terms ----
        float D1[2][2][4], D2[2][2][4];
        #pragma unroll
        for (int mtl = 0; mtl < 2; mtl++)
            #pragma unroll
            for (int ntl = 0; ntl < 2; ntl++) {
                D1[mtl][ntl][0] = biasLo[mtl]; D1[mtl][ntl][1] = biasLo[mtl];
                D1[mtl][ntl][2] = biasHi[mtl]; D1[mtl][ntl][3] = biasHi[mtl];
                D2[mtl][ntl][0] = 0.f; D2[mtl][ntl][1] = 0.f;
                D2[mtl][ntl][2] = 0.f; D2[mtl][ntl][3] = 0.f;
            }
        const uint32_t* svh = (const uint32_t*)(smem + V_OFF + (t & 1) * 15360);
        const uint32_t* svl = svh + 1920;
        #pragma unroll
        for (int kc = 0; kc < 10; kc++) {
            uint4 Ah0 = sWf[fb0 + kc * 32];
            uint4 Ah1 = sWf[fb1 + kc * 32];
            uint4 Al0 = sWf[fb0 + 320 + kc * 32];
            uint4 Al1 = sWf[fb1 + 320 + kc * 32];
            const int rB0 = (kc * 8 + tid4) * 24, rB1 = (kc * 8 + 4 + tid4) * 24;
            #pragma unroll
            for (int ntl = 0; ntl < 2; ntl++) {
                const int col = ntl * 8 + gid;
                uint32_t bh0 = svh[rB0 + col], bh1 = svh[rB1 + col];
                uint32_t bl0 = svl[rB0 + col], bl1 = svl[rB1 + col];
                MMA(D1[0][ntl], Ah0, bh0, bh1);
                MMA(D1[1][ntl], Ah1, bh0, bh1);
                MMA(D2[0][ntl], Ah0, bl0, bl1);
                MMA(D2[1][ntl], Ah1, bl0, bl1);
                MMA(D2[0][ntl], Al0, bh0, bh1);
                MMA(D2[1][ntl], Al1, bh0, bh1);
            }
        }
        // ---- stage D to smem ----
        #pragma unroll
        for (int mtl = 0; mtl < 2; mtl++)
            #pragma unroll
            for (int ntl = 0; ntl < 2; ntl++) {
                int row = (2 * w + mtl) * 16 + gid, colb = ntl * 8 + tid4 * 2;
                *(float2*)(sD + row * 18 + colb) =
                    make_float2(D1[mtl][ntl][0] + D2[mtl][ntl][0],
                                D1[mtl][ntl][1] + D2[mtl][ntl][1]);
                *(float2*)(sD + (row + 8) * 18 + colb) =
                    make_float2(D1[mtl][ntl][2] + D2[mtl][ntl][2],
                                D1[mtl][ntl][3] + D2[mtl][ntl][3]);
            }
        __syncthreads();
        // ---- epilogue: gather gates, update c/h, exchange h, head ----
        {
            float pp0 = 0.f, pp1 = 0.f;
            uint32_t hhi[2] = {0u, 0u}, hlo[2] = {0u, 0u};
            #pragma unroll
            for (int jq = 0; jq < 2; jq++) {
                const int jj = jj0 + jq;
                float2 i2 = *(const float2*)(sD + jj * 18 + b0p);
                float2 f2 = *(const float2*)(sD + (64 + jj) * 18 + b0p);
                float2 g2 = *(const float2*)(sD + (128 + jj) * 18 + b0p);
                float2 o2 = *(const float2*)(sD + (192 + jj) * 18 + b0p);
                const float wjq = jq ? wj1 : wj0;
                #pragma unroll
                for (int bq = 0; bq < 2; bq++) {
                    float iv = bq ? i2.y : i2.x;
                    float fv = bq ? f2.y : f2.x;
                    float gv = bq ? g2.y : g2.x;
                    float ov = bq ? o2.y : o2.x;
                    float cv = sigm_(fv) * cst[jq][bq] + sigm_(iv) * tanh_(gv);
                    cst[jq][bq] = cv;
                    float hv = sigm_(ov) * tanh_(cv);
                    hst[jq][bq] = hv;
                    if (bq) pp1 = fmaf(hv, wjq, pp1); else pp0 = fmaf(hv, wjq, pp0);
                    __nv_bfloat16 hb = __float2bfloat16(hv);
                    uint32_t hb16 = __bfloat16_as_ushort(hb);
                    uint32_t lb16 = __bfloat16_as_ushort(
                        __float2bfloat16(hv - __bfloat162float(hb)));
                    hhi[bq] |= hb16 << (16 * jq);
                    hlo[bq] |= lb16 << (16 * jq);
                }
            }
            // h(t+1) into next buffer, own + peer
            const uint32_t vbo = V_OFF + (uint32_t)(((t + 1) & 1) * 15360)
                               + (uint32_t)(((int)jh * 32 + l) * 24 + b0p) * 4;
            unsigned long long Hv = (unsigned long long)hhi[0] | ((unsigned long long)hhi[1] << 32);
            unsigned long long Lv = (unsigned long long)hlo[0] | ((unsigned long long)hlo[1] << 32);
            *(unsigned long long*)(smem + vbo) = Hv;
            *(unsigned long long*)(smem + vbo + 7680) = Lv;
            stc64(peerBase + vbo, Hv);
            stc64(peerBase + vbo + 7680, Lv);
            // x(t+1) into next buffer (local only)
            if (t + 1 < T_) {
                const uint32_t xo = V_OFF + (uint32_t)(((t + 1) & 1) * 15360) + xoff;
                __nv_bfloat16 h0 = __float2bfloat16(xv.x), h1 = __float2bfloat16(xv.y);
                uint32_t xh = __bfloat16_as_ushort(h0)
                            | ((uint32_t)__bfloat16_as_ushort(h1) << 16);
                uint32_t xl = __bfloat16_as_ushort(__float2bfloat16(xv.x - __bfloat162float(h0)))
                            | ((uint32_t)__bfloat16_as_ushort(__float2bfloat16(xv.y - __bfloat162float(h1))) << 16);
                *(uint32_t*)(smem + xo) = xh;
                *(uint32_t*)(smem + xo + 7680) = xl;
            }
            // head partials -> rank 0
            #pragma unroll
            for (int m = 1; m <= 16; m <<= 1) {
                pp0 += __shfl_xor_sync(0xffffffffu, pp0, m);
                pp1 += __shfl_xor_sync(0xffffffffu, pp1, m);
            }
            if (l == 0) {
                const uint32_t ro = SRED_OFF
                    + (uint32_t)((((t & 1) * 2 + (int)jh) * 16 + 2 * w) * 4);
                unsigned long long pv;
                asm("mov.b64 %0, {%1,%2};" : "=l"(pv) : "f"(pp0), "f"(pp1));
                stc64(r0Base + ro, pv);
            }
        }
        // ---- handshake: CTA-local sync, single elected cluster arrive, parity wait ----
        __syncthreads();
        {
            const int mb = t & 1;
            if (tid == 0) {
                mbar_arrive_cl(mb ? mbarSelfC1 : mbarSelfC0);
                mbar_arrive_cl(mb ? mbarPeerC1 : mbarPeerC0);
            }
            MBAR_WAIT(mb ? mbarLoc1 : mbarLoc0, ph2[mb]);
            ph2[mb] ^= 1u;
        }
    }
    // ---- pred(T-1) ----
    if (jh == 0 && tid < 16) {
        int bf = (T_ - 1) & 1;
        float s = sRed[bf * 32 + tid] + sRed[bf * 32 + 16 + tid] + bo;
        out[((size_t)(bh * 16 + tid) * T_ + (T_ - 1)) * NS_ + n] = s;
    }
    // ---- hT, cT ----
    {
        const size_t OB = (size_t)32 * T_ * NS_;
        const size_t OC = OB + (size_t)32 * 32 * 128;
        #pragma unroll
        for (int jq = 0; jq < 2; jq++)
            #pragma unroll
            for (int bq = 0; bq < 2; bq++) {
                int bgl = bh * 16 + b0p + bq;
                int jgl = (int)jh * 64 + jj0 + jq;
                out[OB + ((size_t)n * 32 + bgl) * 128 + jgl] = hst[jq][bq];
                out[OC + ((size_t)n * 32 + bgl) * 128 + jgl] = cst[jq][bq];
            }
    }
    CSYNC();
}

extern "C" void kernel_launch(void* const* d_in, const int* in_sizes, int n_in,
                              void* d_out, int out_size) {
    const float* X    = (const float*)d_in[0];
    const float* Wih  = (const float*)d_in[1];
    const float* Whh  = (const float*)d_in[2];
    const float* bih  = (const float*)d_in[3];
    const float* bhh  = (const float*)d_in[4];
    const float* Wout = (const float*)d_in[5];
    const float* bout = (const float*)d_in[6];

    prep_k<<<dim3(320, 64), 32>>>(Whh, Wih);

    cudaFuncSetAttribute(lstm_mma, cudaFuncAttributeMaxDynamicSharedMemorySize, SMEM_BYTES);
    lstm_mma<<<128, 256, SMEM_BYTES>>>(X, bih, bhh, Wout, bout, (float*)d_out);
}